// round 5
// baseline (speedup 1.0000x reference)
#include <cuda_runtime.h>
#include <math.h>

// ---------------- problem constants ----------------
#define T_SEQ   2048
#define C_DIM   2048
#define NH      16
#define HS      128
#define NLQ     1536
#define NLKV    512
#define DHR     64
#define DQK     (NLKV + DHR)   // 576
#define HALF_R  (DHR/2)        // 32

// ---------------- scratch (device globals; no allocation allowed) ----------------
__device__ float g_cq  [T_SEQ * (size_t)NLQ];          // 2048x1536
__device__ float g_qall[T_SEQ * (size_t)C_DIM];        // 2048x2048
__device__ float g_qr  [T_SEQ * (size_t)(NH*DHR)];     // 2048x1024
__device__ float g_kr  [T_SEQ * (size_t)DHR];          // 2048x64
__device__ float g_Qc  [(size_t)NH * T_SEQ * DQK];     // 16x2048x576
__device__ float g_Kc  [(size_t)T_SEQ * DQK];          // 2048x576  (cols 0:512 = c_kv, 512:576 = roped k_r)
__device__ float g_S   [(size_t)NH * T_SEQ * T_SEQ];   // 16x2048x2048 scores / probs
__device__ float g_ylat[(size_t)NH * T_SEQ * NLKV];    // 16x2048x512
__device__ float g_WuvT[(size_t)NLKV * C_DIM];         // 512x2048
__device__ float g_Veff[(size_t)NLKV * C_DIM];         // 512x2048

// ---------------- generic tiled SGEMM ----------------
// C[m,n] = alpha * sum_k A[m,k] * B(k,n)
// A: row-major, lda; B: BT ? B[n*ldb + k] : B[k*ldb + n]
// CMODE: 0 = plain, 1 = causal skip (skip CTA tiles fully above diagonal),
//        2 = causal K-limit (k loop capped at row-block end; used for P@V)
// blockIdx.z = batch; per-batch element strides sA/sB/sC (sB may be 0 = shared B).
#define BM 128
#define BN 128
#define BK 8
#define TM 8
#define TN 8

template<bool BT, int CMODE>
__global__ __launch_bounds__(256)
void gemm_kernel(int M, int N, int K,
                 const float* __restrict__ A, int lda, long long sA,
                 const float* __restrict__ B, int ldb, long long sB,
                 float* __restrict__ C, int ldc, long long sC,
                 float alpha)
{
    const int m0 = blockIdx.y * BM;
    const int n0 = blockIdx.x * BN;
    if (CMODE == 1 && n0 > m0) return;            // tile entirely above diagonal
    int kEnd = K;
    if (CMODE == 2) kEnd = min(K, m0 + BM);       // rows [m0,m0+BM) need cols < m0+BM

    const long long z = blockIdx.z;
    A += z * sA;  B += z * sB;  C += z * sC;

    __shared__ float As[BK][BM];
    __shared__ float Bs[BK][BN];

    const int tid = threadIdx.x;
    // A tile loads: 128 rows x 8 k, float4 along k
    const int aRow = tid >> 1;
    const int aK   = (tid & 1) * 4;
    // B tile loads (NN): 8 k-rows x 128 n, float4 along n
    const int bK   = tid >> 5;
    const int bN   = (tid & 31) * 4;

    const int tx = tid & 15;
    const int ty = tid >> 4;

    float acc[TM][TN];
#pragma unroll
    for (int i = 0; i < TM; i++)
#pragma unroll
        for (int j = 0; j < TN; j++) acc[i][j] = 0.f;

    for (int k0 = 0; k0 < kEnd; k0 += BK) {
        // --- load A (guard: full rows; K is always a multiple of 8 here) ---
        {
            const int gm = m0 + aRow;
            float4 v = make_float4(0.f, 0.f, 0.f, 0.f);
            if (gm < M)
                v = *reinterpret_cast<const float4*>(A + (long long)gm * lda + k0 + aK);
            As[aK + 0][aRow] = v.x;
            As[aK + 1][aRow] = v.y;
            As[aK + 2][aRow] = v.z;
            As[aK + 3][aRow] = v.w;
        }
        // --- load B ---
        if (BT) {
            const int gn = n0 + aRow;            // same row/k4 pattern as A
            float4 v = make_float4(0.f, 0.f, 0.f, 0.f);
            if (gn < N)
                v = *reinterpret_cast<const float4*>(B + (long long)gn * ldb + k0 + aK);
            Bs[aK + 0][aRow] = v.x;
            Bs[aK + 1][aRow] = v.y;
            Bs[aK + 2][aRow] = v.z;
            Bs[aK + 3][aRow] = v.w;
        } else {
            const int gn = n0 + bN;
            float4 v = make_float4(0.f, 0.f, 0.f, 0.f);
            if (gn < N)
                v = *reinterpret_cast<const float4*>(B + (long long)(k0 + bK) * ldb + gn);
            *reinterpret_cast<float4*>(&Bs[bK][bN]) = v;
        }
        __syncthreads();

#pragma unroll
        for (int kk = 0; kk < BK; kk++) {
            float4 a0 = *reinterpret_cast<const float4*>(&As[kk][ty * TM]);
            float4 a1 = *reinterpret_cast<const float4*>(&As[kk][ty * TM + 4]);
            float4 b0 = *reinterpret_cast<const float4*>(&Bs[kk][tx * TN]);
            float4 b1 = *reinterpret_cast<const float4*>(&Bs[kk][tx * TN + 4]);
            float ra[TM] = {a0.x, a0.y, a0.z, a0.w, a1.x, a1.y, a1.z, a1.w};
            float rb[TN] = {b0.x, b0.y, b0.z, b0.w, b1.x, b1.y, b1.z, b1.w};
#pragma unroll
            for (int i = 0; i < TM; i++)
#pragma unroll
                for (int j = 0; j < TN; j++)
                    acc[i][j] += ra[i] * rb[j];
        }
        __syncthreads();
    }

    // --- store (N always a multiple of 4 in this problem) ---
#pragma unroll
    for (int i = 0; i < TM; i++) {
        const int gm = m0 + ty * TM + i;
        if (gm >= M) continue;
#pragma unroll
        for (int j = 0; j < TN; j += 4) {
            const int gn = n0 + tx * TN + j;
            if (gn < N) {
                float4 v;
                v.x = acc[i][j + 0] * alpha;
                v.y = acc[i][j + 1] * alpha;
                v.z = acc[i][j + 2] * alpha;
                v.w = acc[i][j + 3] * alpha;
                *reinterpret_cast<float4*>(C + (long long)gm * ldc + gn) = v;
            }
        }
    }
}

// ---------------- W_uv transpose: (2048x512) -> (512x2048) ----------------
__global__ void transpose_wuv_kernel(const float* __restrict__ W, float* __restrict__ Wt)
{
    int idx = blockIdx.x * blockDim.x + threadIdx.x;
    if (idx < C_DIM * NLKV) {
        int k = idx % NLKV;
        int c = idx / NLKV;
        Wt[(long long)k * C_DIM + c] = W[idx];
    }
}

// ---------------- RoPE assembly into Qc[...,512:576] and Kc[...,512:576] ----------------
__global__ void rope_kernel(const float* __restrict__ qr, const float* __restrict__ kr,
                            const float* __restrict__ cosT, const float* __restrict__ sinT,
                            float* __restrict__ Qc, float* __restrict__ Kc)
{
    int idx = blockIdx.x * blockDim.x + threadIdx.x;
    const int totalQ = T_SEQ * NH * HALF_R;
    if (idx < totalQ) {
        int j = idx % HALF_R;
        int h = (idx / HALF_R) % NH;
        int t = idx / (HALF_R * NH);
        float re = qr[(long long)t * (NH * DHR) + h * DHR + 2 * j];
        float im = qr[(long long)t * (NH * DHR) + h * DHR + 2 * j + 1];
        float c = cosT[t * HALF_R + j];
        float s = sinT[t * HALF_R + j];
        float* dst = Qc + ((long long)h * T_SEQ + t) * DQK + NLKV;
        dst[2 * j]     = re * c - im * s;
        dst[2 * j + 1] = re * s + im * c;
    } else {
        int k = idx - totalQ;
        if (k < T_SEQ * HALF_R) {
            int j = k % HALF_R;
            int t = k / HALF_R;
            float re = kr[t * DHR + 2 * j];
            float im = kr[t * DHR + 2 * j + 1];
            float c = cosT[t * HALF_R + j];
            float s = sinT[t * HALF_R + j];
            Kc[(long long)t * DQK + NLKV + 2 * j]     = re * c - im * s;
            Kc[(long long)t * DQK + NLKV + 2 * j + 1] = re * s + im * c;
        }
    }
}

// ---------------- causal softmax (in place on g_S) ----------------
// grid: (T, NH), 256 threads. Writes zeros for s > t so the P@V GEMM reads clean tiles.
__global__ __launch_bounds__(256)
void softmax_kernel(float* __restrict__ S)
{
    const int t = blockIdx.x;
    float* row = S + ((long long)blockIdx.y * T_SEQ + t) * (long long)T_SEQ;
    const int len = t + 1;
    const int tid = threadIdx.x;
    __shared__ float sm[32];

    // --- max over [0, len) ---
    float m = -3.4e38f;
    for (int i = tid; i < len; i += 256) m = fmaxf(m, row[i]);
#pragma unroll
    for (int o = 16; o; o >>= 1) m = fmaxf(m, __shfl_xor_sync(0xffffffffu, m, o));
    if ((tid & 31) == 0) sm[tid >> 5] = m;
    __syncthreads();
    if (tid < 32) {
        float v = (tid < 8) ? sm[tid] : -3.4e38f;
#pragma unroll
        for (int o = 4; o; o >>= 1) v = fmaxf(v, __shfl_xor_sync(0xffffffffu, v, o));
        if (tid == 0) sm[0] = v;
    }
    __syncthreads();
    m = sm[0];
    __syncthreads();   // everyone has read sm[0] before reuse

    // --- exp + sum (store exp back into row) ---
    float s = 0.f;
    for (int i = tid; i < len; i += 256) {
        float e = expf(row[i] - m);
        row[i] = e;
        s += e;
    }
#pragma unroll
    for (int o = 16; o; o >>= 1) s += __shfl_xor_sync(0xffffffffu, s, o);
    if ((tid & 31) == 0) sm[tid >> 5] = s;
    __syncthreads();
    if (tid < 32) {
        float v = (tid < 8) ? sm[tid] : 0.f;
#pragma unroll
        for (int o = 4; o; o >>= 1) v += __shfl_xor_sync(0xffffffffu, v, o);
        if (tid == 0) sm[0] = v;
    }
    __syncthreads();
    const float inv = 1.f / sm[0];
    for (int i = tid; i < len; i += 256) row[i] *= inv;
    for (int i = len + tid; i < T_SEQ; i += 256) row[i] = 0.f;   // clean upper triangle
}

// ---------------- host orchestration ----------------
static inline dim3 gemm_grid(int M, int N, int Z)
{
    return dim3((N + BN - 1) / BN, (M + BM - 1) / BM, Z);
}

extern "C" void kernel_launch(void* const* d_in, const int* in_sizes, int n_in,
                              void* d_out, int out_size)
{
    const float* x     = (const float*)d_in[0];   // (1,2048,2048)
    const float* fcos  = (const float*)d_in[1];   // (2048,32)
    const float* fsin  = (const float*)d_in[2];   // (2048,32)
    const float* W_dq  = (const float*)d_in[3];   // (1536,2048)
    const float* W_uq  = (const float*)d_in[4];   // (2048,1536) -> reinterpret (1536,2048)
    const float* W_dkv = (const float*)d_in[5];   // (512,2048)
    const float* W_uk  = (const float*)d_in[6];   // (2048,512)
    const float* W_uv  = (const float*)d_in[7];   // (2048,512)
    const float* W_qr  = (const float*)d_in[8];   // (1024,1536)
    const float* W_kr  = (const float*)d_in[9];   // (64,2048)
    const float* W_o   = (const float*)d_in[10];  // (2048,2048)
    float* out = (float*)d_out;                   // (2048,2048)

    float *p_cq, *p_qall, *p_qr, *p_kr, *p_Qc, *p_Kc, *p_S, *p_ylat, *p_WuvT, *p_Veff;
    cudaGetSymbolAddress((void**)&p_cq,   g_cq);
    cudaGetSymbolAddress((void**)&p_qall, g_qall);
    cudaGetSymbolAddress((void**)&p_qr,   g_qr);
    cudaGetSymbolAddress((void**)&p_kr,   g_kr);
    cudaGetSymbolAddress((void**)&p_Qc,   g_Qc);
    cudaGetSymbolAddress((void**)&p_Kc,   g_Kc);
    cudaGetSymbolAddress((void**)&p_S,    g_S);
    cudaGetSymbolAddress((void**)&p_ylat, g_ylat);
    cudaGetSymbolAddress((void**)&p_WuvT, g_WuvT);
    cudaGetSymbolAddress((void**)&p_Veff, g_Veff);

    const float scale = 1.0f / sqrtf((float)(HS + DHR));
    const dim3 blk(256);

    // 0) WuvT[k,c] = W_uv[c,k]
    transpose_wuv_kernel<<<(C_DIM * NLKV + 255) / 256, blk>>>(W_uv, p_WuvT);

    // 1) c_q = x @ W_dq^T              (2048 x 1536, K=2048)  NT
    gemm_kernel<true, 0><<<gemm_grid(T_SEQ, NLQ, 1), blk>>>(
        T_SEQ, NLQ, C_DIM, x, C_DIM, 0, W_dq, C_DIM, 0, p_cq, NLQ, 0, 1.f);

    // 2) Kc[:, 0:512] = x @ W_dkv^T    (2048 x 512, K=2048)   NT, ldc=576
    gemm_kernel<true, 0><<<gemm_grid(T_SEQ, NLKV, 1), blk>>>(
        T_SEQ, NLKV, C_DIM, x, C_DIM, 0, W_dkv, C_DIM, 0, p_Kc, DQK, 0, 1.f);

    // 3) kr = x @ W_kr^T               (2048 x 64, K=2048)    NT
    gemm_kernel<true, 0><<<gemm_grid(T_SEQ, DHR, 1), blk>>>(
        T_SEQ, DHR, C_DIM, x, C_DIM, 0, W_kr, C_DIM, 0, p_kr, DHR, 0, 1.f);

    // 4) Veff = WuvT @ W_o^T           (512 x 2048, K=2048)   NT
    gemm_kernel<true, 0><<<gemm_grid(NLKV, C_DIM, 1), blk>>>(
        NLKV, C_DIM, C_DIM, p_WuvT, C_DIM, 0, W_o, C_DIM, 0, p_Veff, C_DIM, 0, 1.f);

    // 5) q_all = c_q @ M_uq            (2048 x 2048, K=1536)  NN (W_uq buffer as 1536x2048)
    gemm_kernel<false, 0><<<gemm_grid(T_SEQ, C_DIM, 1), blk>>>(
        T_SEQ, C_DIM, NLQ, p_cq, NLQ, 0, W_uq, C_DIM, 0, p_qall, C_DIM, 0, 1.f);

    // 6) qr_all = c_q @ W_qr^T         (2048 x 1024, K=1536)  NT
    gemm_kernel<true, 0><<<gemm_grid(T_SEQ, NH * DHR, 1), blk>>>(
        T_SEQ, NH * DHR, NLQ, p_cq, NLQ, 0, W_qr, NLQ, 0, p_qr, NH * DHR, 0, 1.f);

    // 7) Qc[h][:, 0:512] = q_all[:, h*128:] @ W_uk[h*128:, :]   batched NN, z=16
    gemm_kernel<false, 0><<<gemm_grid(T_SEQ, NLKV, NH), blk>>>(
        T_SEQ, NLKV, HS,
        p_qall, C_DIM, (long long)HS,
        W_uk,   NLKV,  (long long)HS * NLKV,
        p_Qc,   DQK,   (long long)T_SEQ * DQK, 1.f);

    // 8) RoPE -> Qc[...,512:576], Kc[...,512:576]
    {
        int total = T_SEQ * NH * HALF_R + T_SEQ * HALF_R;
        rope_kernel<<<(total + 255) / 256, blk>>>(p_qr, p_kr, fcos, fsin, p_Qc, p_Kc);
    }

    // 9) S[h] = scale * Qc[h] @ Kc^T   (2048 x 2048, K=576)  batched NT, causal tile skip
    gemm_kernel<true, 1><<<gemm_grid(T_SEQ, T_SEQ, NH), blk>>>(
        T_SEQ, T_SEQ, DQK,
        p_Qc, DQK, (long long)T_SEQ * DQK,
        p_Kc, DQK, 0LL,
        p_S,  T_SEQ, (long long)T_SEQ * T_SEQ, scale);

    // 10) causal softmax (zeros above diagonal)
    softmax_kernel<<<dim3(T_SEQ, NH), blk>>>(p_S);

    // 11) y_lat[h] = P[h] @ Kc[:, 0:512]   (2048 x 512, K=2048) batched NN, K capped per row-block
    gemm_kernel<false, 2><<<gemm_grid(T_SEQ, NLKV, NH), blk>>>(
        T_SEQ, NLKV, T_SEQ,
        p_S,  T_SEQ, (long long)T_SEQ * T_SEQ,
        p_Kc, DQK,   0LL,
        p_ylat, NLKV, (long long)T_SEQ * NLKV, 1.f);

    // 12) out[:, h*128:(h+1)*128] = y_lat[h] @ Veff[:, h*128:]  batched NN
    gemm_kernel<false, 0><<<gemm_grid(T_SEQ, HS, NH), blk>>>(
        T_SEQ, HS, NLKV,
        p_ylat, NLKV, (long long)T_SEQ * NLKV,
        p_Veff, C_DIM, (long long)HS,
        out,    C_DIM, (long long)HS, 1.f);
}

// round 6
// speedup vs baseline: 2.4469x; 2.4469x over previous
#include <cuda_runtime.h>
#include <math.h>
#include <stdint.h>

// ---------------- problem constants ----------------
#define T_SEQ   2048
#define C_DIM   2048
#define NH      16
#define HS      128
#define NLQ     1536
#define NLKV    512
#define DHR     64
#define DQK     (NLKV + DHR)   // 576
#define HALF_R  (DHR/2)        // 32

// ---------------- scratch (device globals; no allocation allowed) ----------------
__device__ float g_cq  [T_SEQ * (size_t)NLQ];          // 2048x1536
__device__ float g_qall[T_SEQ * (size_t)C_DIM];        // 2048x2048
__device__ float g_qr  [T_SEQ * (size_t)(NH*DHR)];     // 2048x1024
__device__ float g_kr  [T_SEQ * (size_t)DHR];          // 2048x64
__device__ float g_Qc  [(size_t)NH * T_SEQ * DQK];     // 16x2048x576
__device__ float g_Kc  [(size_t)T_SEQ * DQK];          // 2048x576
__device__ float g_S   [(size_t)NH * T_SEQ * T_SEQ];   // 16x2048x2048
__device__ float g_ylat[(size_t)NH * T_SEQ * NLKV];    // 16x2048x512
__device__ float g_WuvT[(size_t)NLKV * C_DIM];         // 512x2048
__device__ float g_Veff[(size_t)NLKV * C_DIM];         // 512x2048

// ---------------- tf32 helpers ----------------
__device__ __forceinline__ uint32_t f2tf(float f)
{
    uint32_t r;
    asm("cvt.rna.tf32.f32 %0, %1;" : "=r"(r) : "f"(f));
    return r;
}

__device__ __forceinline__ void mma_tf32(float* d, const uint32_t* a, const uint32_t* b)
{
    asm volatile(
        "mma.sync.aligned.m16n8k8.row.col.f32.tf32.tf32.f32 "
        "{%0,%1,%2,%3},{%4,%5,%6,%7},{%8,%9},{%0,%1,%2,%3};"
        : "+f"(d[0]), "+f"(d[1]), "+f"(d[2]), "+f"(d[3])
        : "r"(a[0]), "r"(a[1]), "r"(a[2]), "r"(a[3]),
          "r"(b[0]), "r"(b[1]));
}

// ---------------- tensor-core GEMM (tf32 mma.sync, fp32 accumulate) ----------------
// C[m,n] = alpha * sum_k A[m,k] * B(k,n)
// A row-major (lda). B: BT ? B[n*ldb+k] : B[k*ldb+n].
// CMODE: 0 plain; 1 causal CTA-tile skip; 2 causal K-limit (kEnd = m0+BM).
// Requirements met by all call sites: M % 128 == 0, K % 16 == 0, N % 4 == 0,
// all leading dims multiples of 4 (float4-aligned rows).
#define BM 128
#define BN 128
#define BK 16

template<bool BT, int CMODE>
__global__ __launch_bounds__(256)
void gemm_tc(int M, int N, int K,
             const float* __restrict__ A, int lda, long long sA,
             const float* __restrict__ B, int ldb, long long sB,
             float* __restrict__ C, int ldc, long long sC,
             float alpha)
{
    const int m0 = blockIdx.y * BM;
    const int n0 = blockIdx.x * BN;
    if (CMODE == 1 && n0 > m0) return;
    int kEnd = K;
    if (CMODE == 2) kEnd = min(K, m0 + BM);

    const long long z = blockIdx.z;
    A += z * sA;  B += z * sB;  C += z * sC;

    __shared__ uint32_t As[BM][BK + 4];   // pad 4 -> conflict-free frag reads
    __shared__ uint32_t Bs[BK][BN + 8];   // pad 8 -> conflict-free frag reads

    const int tid  = threadIdx.x;
    const int lane = tid & 31;
    const int w    = tid >> 5;
    const int gid  = lane >> 2;   // 0..7
    const int tg   = lane & 3;    // 0..3
    const int wm   = w >> 2;      // 0..1
    const int wn   = w & 3;       // 0..3
    const int mBase = wm * 64;
    const int nBase = wn * 32;

    // global-load thread mapping
    const int aRow = tid >> 1;            // 0..127
    const int aJ   = (tid & 1) * 8;       // 0 or 8
    const int bK   = tid >> 5;            // 0..7 (NN)
    const int bN4  = (tid & 31) * 4;      // 0..124 (NN)

    float acc[4][4][4];
#pragma unroll
    for (int i = 0; i < 4; i++)
#pragma unroll
        for (int j = 0; j < 4; j++)
#pragma unroll
            for (int r = 0; r < 4; r++) acc[i][j][r] = 0.f;

    float4 pa0, pa1, pb0, pb1;
    const float4 z4 = make_float4(0.f, 0.f, 0.f, 0.f);

    auto ldg = [&](int k0) {
        const float* pA = A + (long long)(m0 + aRow) * lda + k0 + aJ;
        pa0 = *reinterpret_cast<const float4*>(pA);
        pa1 = *reinterpret_cast<const float4*>(pA + 4);
        if (BT) {
            const int gn = n0 + aRow;
            if (gn < N) {
                const float* pB = B + (long long)gn * ldb + k0 + aJ;
                pb0 = *reinterpret_cast<const float4*>(pB);
                pb1 = *reinterpret_cast<const float4*>(pB + 4);
            } else { pb0 = z4; pb1 = z4; }
        } else {
            const int gn = n0 + bN4;
            if (gn < N) {
                pb0 = *reinterpret_cast<const float4*>(B + (long long)(k0 + bK) * ldb + gn);
                pb1 = *reinterpret_cast<const float4*>(B + (long long)(k0 + bK + 8) * ldb + gn);
            } else { pb0 = z4; pb1 = z4; }
        }
    };

    auto sts = [&]() {
        uint32_t* ap = &As[aRow][aJ];
        ap[0] = f2tf(pa0.x); ap[1] = f2tf(pa0.y); ap[2] = f2tf(pa0.z); ap[3] = f2tf(pa0.w);
        ap[4] = f2tf(pa1.x); ap[5] = f2tf(pa1.y); ap[6] = f2tf(pa1.z); ap[7] = f2tf(pa1.w);
        if (BT) {
            Bs[aJ + 0][aRow] = f2tf(pb0.x);
            Bs[aJ + 1][aRow] = f2tf(pb0.y);
            Bs[aJ + 2][aRow] = f2tf(pb0.z);
            Bs[aJ + 3][aRow] = f2tf(pb0.w);
            Bs[aJ + 4][aRow] = f2tf(pb1.x);
            Bs[aJ + 5][aRow] = f2tf(pb1.y);
            Bs[aJ + 6][aRow] = f2tf(pb1.z);
            Bs[aJ + 7][aRow] = f2tf(pb1.w);
        } else {
            uint32_t* bp0 = &Bs[bK][bN4];
            bp0[0] = f2tf(pb0.x); bp0[1] = f2tf(pb0.y); bp0[2] = f2tf(pb0.z); bp0[3] = f2tf(pb0.w);
            uint32_t* bp1 = &Bs[bK + 8][bN4];
            bp1[0] = f2tf(pb1.x); bp1[1] = f2tf(pb1.y); bp1[2] = f2tf(pb1.z); bp1[3] = f2tf(pb1.w);
        }
    };

    ldg(0);
    for (int k0 = 0; k0 < kEnd; k0 += BK) {
        sts();
        __syncthreads();
        if (k0 + BK < kEnd) ldg(k0 + BK);   // prefetch next tile into regs

#pragma unroll
        for (int kk = 0; kk < BK; kk += 8) {
            uint32_t af[4][4], bf[4][2];
#pragma unroll
            for (int mt = 0; mt < 4; mt++) {
                const int r = mBase + mt * 16;
                af[mt][0] = As[r + gid][kk + tg];
                af[mt][1] = As[r + gid + 8][kk + tg];
                af[mt][2] = As[r + gid][kk + tg + 4];
                af[mt][3] = As[r + gid + 8][kk + tg + 4];
            }
#pragma unroll
            for (int nt = 0; nt < 4; nt++) {
                const int c = nBase + nt * 8 + gid;
                bf[nt][0] = Bs[kk + tg][c];
                bf[nt][1] = Bs[kk + tg + 4][c];
            }
#pragma unroll
            for (int mt = 0; mt < 4; mt++)
#pragma unroll
                for (int nt = 0; nt < 4; nt++)
                    mma_tf32(acc[mt][nt], af[mt], bf[nt]);
        }
        __syncthreads();
    }

    // epilogue (M always a multiple of 128; N even)
#pragma unroll
    for (int mt = 0; mt < 4; mt++) {
        const int r = m0 + mBase + mt * 16 + gid;
#pragma unroll
        for (int nt = 0; nt < 4; nt++) {
            const int c = n0 + nBase + nt * 8 + 2 * tg;
            if (c < N) {
                float2 v0, v1;
                v0.x = acc[mt][nt][0] * alpha;
                v0.y = acc[mt][nt][1] * alpha;
                v1.x = acc[mt][nt][2] * alpha;
                v1.y = acc[mt][nt][3] * alpha;
                *reinterpret_cast<float2*>(C + (long long)r * ldc + c)       = v0;
                *reinterpret_cast<float2*>(C + (long long)(r + 8) * ldc + c) = v1;
            }
        }
    }
}

// ---------------- W_uv transpose: (2048x512) -> (512x2048) ----------------
__global__ void transpose_wuv_kernel(const float* __restrict__ W, float* __restrict__ Wt)
{
    int idx = blockIdx.x * blockDim.x + threadIdx.x;
    if (idx < C_DIM * NLKV) {
        int k = idx % NLKV;
        int c = idx / NLKV;
        Wt[(long long)k * C_DIM + c] = W[idx];
    }
}

// ---------------- RoPE assembly into Qc[...,512:576] and Kc[...,512:576] ----------------
__global__ void rope_kernel(const float* __restrict__ qr, const float* __restrict__ kr,
                            const float* __restrict__ cosT, const float* __restrict__ sinT,
                            float* __restrict__ Qc, float* __restrict__ Kc)
{
    int idx = blockIdx.x * blockDim.x + threadIdx.x;
    const int totalQ = T_SEQ * NH * HALF_R;
    if (idx < totalQ) {
        int j = idx % HALF_R;
        int h = (idx / HALF_R) % NH;
        int t = idx / (HALF_R * NH);
        float re = qr[(long long)t * (NH * DHR) + h * DHR + 2 * j];
        float im = qr[(long long)t * (NH * DHR) + h * DHR + 2 * j + 1];
        float c = cosT[t * HALF_R + j];
        float s = sinT[t * HALF_R + j];
        float* dst = Qc + ((long long)h * T_SEQ + t) * DQK + NLKV;
        dst[2 * j]     = re * c - im * s;
        dst[2 * j + 1] = re * s + im * c;
    } else {
        int k = idx - totalQ;
        if (k < T_SEQ * HALF_R) {
            int j = k % HALF_R;
            int t = k / HALF_R;
            float re = kr[t * DHR + 2 * j];
            float im = kr[t * DHR + 2 * j + 1];
            float c = cosT[t * HALF_R + j];
            float s = sinT[t * HALF_R + j];
            Kc[(long long)t * DQK + NLKV + 2 * j]     = re * c - im * s;
            Kc[(long long)t * DQK + NLKV + 2 * j + 1] = re * s + im * c;
        }
    }
}

// ---------------- causal softmax (in place on g_S) ----------------
__global__ __launch_bounds__(256)
void softmax_kernel(float* __restrict__ S)
{
    const int t = blockIdx.x;
    float* row = S + ((long long)blockIdx.y * T_SEQ + t) * (long long)T_SEQ;
    const int len = t + 1;
    const int tid = threadIdx.x;
    __shared__ float sm[32];

    float m = -3.4e38f;
    for (int i = tid; i < len; i += 256) m = fmaxf(m, row[i]);
#pragma unroll
    for (int o = 16; o; o >>= 1) m = fmaxf(m, __shfl_xor_sync(0xffffffffu, m, o));
    if ((tid & 31) == 0) sm[tid >> 5] = m;
    __syncthreads();
    if (tid < 32) {
        float v = (tid < 8) ? sm[tid] : -3.4e38f;
#pragma unroll
        for (int o = 4; o; o >>= 1) v = fmaxf(v, __shfl_xor_sync(0xffffffffu, v, o));
        if (tid == 0) sm[0] = v;
    }
    __syncthreads();
    m = sm[0];
    __syncthreads();

    float s = 0.f;
    for (int i = tid; i < len; i += 256) {
        float e = expf(row[i] - m);
        row[i] = e;
        s += e;
    }
#pragma unroll
    for (int o = 16; o; o >>= 1) s += __shfl_xor_sync(0xffffffffu, s, o);
    if ((tid & 31) == 0) sm[tid >> 5] = s;
    __syncthreads();
    if (tid < 32) {
        float v = (tid < 8) ? sm[tid] : 0.f;
#pragma unroll
        for (int o = 4; o; o >>= 1) v += __shfl_xor_sync(0xffffffffu, v, o);
        if (tid == 0) sm[0] = v;
    }
    __syncthreads();
    const float inv = 1.f / sm[0];
    for (int i = tid; i < len; i += 256) row[i] *= inv;
    for (int i = len + tid; i < T_SEQ; i += 256) row[i] = 0.f;
}

// ---------------- host orchestration ----------------
static inline dim3 gemm_grid(int M, int N, int Z)
{
    return dim3((N + BN - 1) / BN, (M + BM - 1) / BM, Z);
}

extern "C" void kernel_launch(void* const* d_in, const int* in_sizes, int n_in,
                              void* d_out, int out_size)
{
    const float* x     = (const float*)d_in[0];
    const float* fcos  = (const float*)d_in[1];
    const float* fsin  = (const float*)d_in[2];
    const float* W_dq  = (const float*)d_in[3];
    const float* W_uq  = (const float*)d_in[4];
    const float* W_dkv = (const float*)d_in[5];
    const float* W_uk  = (const float*)d_in[6];
    const float* W_uv  = (const float*)d_in[7];
    const float* W_qr  = (const float*)d_in[8];
    const float* W_kr  = (const float*)d_in[9];
    const float* W_o   = (const float*)d_in[10];
    float* out = (float*)d_out;

    float *p_cq, *p_qall, *p_qr, *p_kr, *p_Qc, *p_Kc, *p_S, *p_ylat, *p_WuvT, *p_Veff;
    cudaGetSymbolAddress((void**)&p_cq,   g_cq);
    cudaGetSymbolAddress((void**)&p_qall, g_qall);
    cudaGetSymbolAddress((void**)&p_qr,   g_qr);
    cudaGetSymbolAddress((void**)&p_kr,   g_kr);
    cudaGetSymbolAddress((void**)&p_Qc,   g_Qc);
    cudaGetSymbolAddress((void**)&p_Kc,   g_Kc);
    cudaGetSymbolAddress((void**)&p_S,    g_S);
    cudaGetSymbolAddress((void**)&p_ylat, g_ylat);
    cudaGetSymbolAddress((void**)&p_WuvT, g_WuvT);
    cudaGetSymbolAddress((void**)&p_Veff, g_Veff);

    const float scale = 1.0f / sqrtf((float)(HS + DHR));
    const dim3 blk(256);

    // 0) WuvT[k,c] = W_uv[c,k]
    transpose_wuv_kernel<<<(C_DIM * NLKV + 255) / 256, blk>>>(W_uv, p_WuvT);

    // 1) c_q = x @ W_dq^T              (2048 x 1536, K=2048)  NT
    gemm_tc<true, 0><<<gemm_grid(T_SEQ, NLQ, 1), blk>>>(
        T_SEQ, NLQ, C_DIM, x, C_DIM, 0, W_dq, C_DIM, 0, p_cq, NLQ, 0, 1.f);

    // 2) Kc[:, 0:512] = x @ W_dkv^T    (2048 x 512, K=2048)   NT, ldc=576
    gemm_tc<true, 0><<<gemm_grid(T_SEQ, NLKV, 1), blk>>>(
        T_SEQ, NLKV, C_DIM, x, C_DIM, 0, W_dkv, C_DIM, 0, p_Kc, DQK, 0, 1.f);

    // 3) kr = x @ W_kr^T               (2048 x 64, K=2048)    NT
    gemm_tc<true, 0><<<gemm_grid(T_SEQ, DHR, 1), blk>>>(
        T_SEQ, DHR, C_DIM, x, C_DIM, 0, W_kr, C_DIM, 0, p_kr, DHR, 0, 1.f);

    // 4) Veff = WuvT @ W_o^T           (512 x 2048, K=2048)   NT
    gemm_tc<true, 0><<<gemm_grid(NLKV, C_DIM, 1), blk>>>(
        NLKV, C_DIM, C_DIM, p_WuvT, C_DIM, 0, W_o, C_DIM, 0, p_Veff, C_DIM, 0, 1.f);

    // 5) q_all = c_q @ M_uq            (2048 x 2048, K=1536)  NN
    gemm_tc<false, 0><<<gemm_grid(T_SEQ, C_DIM, 1), blk>>>(
        T_SEQ, C_DIM, NLQ, p_cq, NLQ, 0, W_uq, C_DIM, 0, p_qall, C_DIM, 0, 1.f);

    // 6) qr_all = c_q @ W_qr^T         (2048 x 1024, K=1536)  NT
    gemm_tc<true, 0><<<gemm_grid(T_SEQ, NH * DHR, 1), blk>>>(
        T_SEQ, NH * DHR, NLQ, p_cq, NLQ, 0, W_qr, NLQ, 0, p_qr, NH * DHR, 0, 1.f);

    // 7) Qc[h][:, 0:512] = q_all[:, h*128:] @ W_uk[h*128:, :]   batched NN, z=16
    gemm_tc<false, 0><<<gemm_grid(T_SEQ, NLKV, NH), blk>>>(
        T_SEQ, NLKV, HS,
        p_qall, C_DIM, (long long)HS,
        W_uk,   NLKV,  (long long)HS * NLKV,
        p_Qc,   DQK,   (long long)T_SEQ * DQK, 1.f);

    // 8) RoPE -> Qc[...,512:576], Kc[...,512:576]
    {
        int total = T_SEQ * NH * HALF_R + T_SEQ * HALF_R;
        rope_kernel<<<(total + 255) / 256, blk>>>(p_qr, p_kr, fcos, fsin, p_Qc, p_Kc);
    }

    // 9) S[h] = scale * Qc[h] @ Kc^T   (2048 x 2048, K=576)  batched NT, causal tile skip
    gemm_tc<true, 1><<<gemm_grid(T_SEQ, T_SEQ, NH), blk>>>(
        T_SEQ, T_SEQ, DQK,
        p_Qc, DQK, (long long)T_SEQ * DQK,
        p_Kc, DQK, 0LL,
        p_S,  T_SEQ, (long long)T_SEQ * T_SEQ, scale);

    // 10) causal softmax (zeros above diagonal)
    softmax_kernel<<<dim3(T_SEQ, NH), blk>>>(p_S);

    // 11) y_lat[h] = P[h] @ Kc[:, 0:512]   batched NN, K capped per row-block
    gemm_tc<false, 2><<<gemm_grid(T_SEQ, NLKV, NH), blk>>>(
        T_SEQ, NLKV, T_SEQ,
        p_S,  T_SEQ, (long long)T_SEQ * T_SEQ,
        p_Kc, DQK,   0LL,
        p_ylat, NLKV, (long long)T_SEQ * NLKV, 1.f);

    // 12) out[:, h*128:(h+1)*128] = y_lat[h] @ Veff[:, h*128:]  batched NN
    gemm_tc<false, 0><<<gemm_grid(T_SEQ, HS, NH), blk>>>(
        T_SEQ, HS, NLKV,
        p_ylat, NLKV, (long long)T_SEQ * NLKV,
        p_Veff, C_DIM, (long long)HS,
        out,    C_DIM, (long long)HS, 1.f);
}